// round 1
// baseline (speedup 1.0000x reference)
#include <cuda_runtime.h>
#include <math.h>

#define NB 8
#define NT 4096
#define ND 64
#define NR 64
#define NTOK (NB * NT)

// Scratch (device globals — no allocation allowed in kernel_launch)
__device__ float g_phi[NTOK * NR];     // 33.5 MB
__device__ float g_mass[NTOK];
__device__ float g_phisum[NB * NR];
__device__ float g_grav[NTOK];

// ---------------------------------------------------------------------------
// K1: per-token mass (Linear->ReLU->Linear->Softplus) and RFF features phi.
// One block of 64 threads per token. Weights are tiny (16 KB each) -> L2 hot.
// ---------------------------------------------------------------------------
__global__ void k_token(const float* __restrict__ coords,
                        const float* __restrict__ w1,
                        const float* __restrict__ b1,
                        const float* __restrict__ w2,
                        const float* __restrict__ b2,
                        const float* __restrict__ W,
                        const float* __restrict__ bvec) {
    const int token = blockIdx.x;
    const int tid   = threadIdx.x;   // 0..63

    __shared__ float sc[ND];
    __shared__ float sh[ND];

    sc[tid] = coords[token * ND + tid];
    __syncthreads();

    // h[tid] = relu( sum_k coords[k] * w1[tid, k] + b1[tid] )
    float acc = b1[tid];
#pragma unroll 16
    for (int k = 0; k < ND; k++)
        acc = fmaf(sc[k], w1[tid * ND + k], acc);
    sh[tid] = fmaxf(acc, 0.0f);

    // phi[tid] = sqrt(2/R) * cos( sum_k coords[k] * W[k, tid] + b[tid] )
    float ap = bvec[tid];
#pragma unroll 16
    for (int k = 0; k < ND; k++)
        ap = fmaf(sc[k], W[k * NR + tid], ap);
    g_phi[token * NR + tid] = 0.17677669529663687f * cosf(ap);  // sqrt(2/64)

    __syncthreads();

    if (tid == 0) {
        float m = b2[0];
#pragma unroll 16
        for (int j = 0; j < ND; j++)
            m = fmaf(sh[j], w2[j], m);
        // softplus, numerically stable
        m = (m > 20.0f) ? m : log1pf(expf(m));
        g_mass[token] = m;
    }
}

// ---------------------------------------------------------------------------
// K2: phi_sum[b, r] = sum_t phi[b, t, r] * mass[b, t]
// Deterministic tree reduction. Grid (R, B), 256 threads.
// phi just written -> mostly L2-resident (8 MB << 126 MB L2).
// ---------------------------------------------------------------------------
__global__ void k_phisum() {
    const int r   = blockIdx.x;
    const int b   = blockIdx.y;
    const int tid = threadIdx.x;

    __shared__ float red[256];
    float s = 0.0f;
    for (int t = tid; t < NT; t += 256) {
        const int tok = b * NT + t;
        s = fmaf(g_phi[tok * NR + r], g_mass[tok], s);
    }
    red[tid] = s;
    __syncthreads();
    for (int o = 128; o > 0; o >>= 1) {
        if (tid < o) red[tid] += red[tid + o];
        __syncthreads();
    }
    if (tid == 0) g_phisum[b * NR + r] = red[0];
}

// ---------------------------------------------------------------------------
// K3: grav[token] = dot(phi[token, :], phi_sum[b, :]). One warp per token.
// ---------------------------------------------------------------------------
__global__ void k_grav() {
    const int warp  = threadIdx.x >> 5;
    const int lane  = threadIdx.x & 31;
    const int token = blockIdx.x * 8 + warp;
    const int b     = token / NT;

    const float* ph = g_phi + (size_t)token * NR;
    const float* ps = g_phisum + b * NR;

    float s = fmaf(ph[lane], ps[lane], ph[lane + 32] * ps[lane + 32]);
#pragma unroll
    for (int o = 16; o > 0; o >>= 1)
        s += __shfl_down_sync(0xffffffffu, s, o);
    if (lane == 0) g_grav[token] = s;
}

// ---------------------------------------------------------------------------
// K4: out = G + STRENGTH * grav * I   (the HBM-streaming hot loop)
// One 256-thread block per token; 4 x float4 per thread (4096 floats/token).
// Diagonal of a 64x64 tile: linear index i*64+i = i*65 -> idx % 65 == 0.
// ---------------------------------------------------------------------------
__global__ void k_out(const float4* __restrict__ G4, float4* __restrict__ O4) {
    const int token = blockIdx.x;
    const int tid   = threadIdx.x;

    const float add = 0.1f * g_grav[token];  // broadcast load

    const float4* src = G4 + (size_t)token * 1024;
    float4*       dst = O4 + (size_t)token * 1024;

#pragma unroll
    for (int k = 0; k < 4; k++) {
        const int i4 = tid + k * 256;
        float4 v = src[i4];
        const int base = i4 * 4;
        if ((base    ) % 65 == 0) v.x += add;
        if ((base + 1) % 65 == 0) v.y += add;
        if ((base + 2) % 65 == 0) v.z += add;
        if ((base + 3) % 65 == 0) v.w += add;
        dst[i4] = v;
    }
}

// ---------------------------------------------------------------------------
extern "C" void kernel_launch(void* const* d_in, const int* in_sizes, int n_in,
                              void* d_out, int out_size) {
    const float* G      = (const float*)d_in[0];
    const float* coords = (const float*)d_in[1];
    const float* w1     = (const float*)d_in[2];
    const float* b1     = (const float*)d_in[3];
    const float* w2     = (const float*)d_in[4];
    const float* b2     = (const float*)d_in[5];
    const float* W      = (const float*)d_in[6];
    const float* bvec   = (const float*)d_in[7];

    k_token<<<NTOK, 64>>>(coords, w1, b1, w2, b2, W, bvec);

    dim3 g2(NR, NB);
    k_phisum<<<g2, 256>>>();

    k_grav<<<NTOK / 8, 256>>>();

    k_out<<<NTOK, 256>>>((const float4*)G, (float4*)d_out);
}

// round 4
// speedup vs baseline: 2.1136x; 2.1136x over previous
#include <cuda_runtime.h>
#include <math.h>

#define NB 8
#define NT 4096
#define ND 64
#define NR 64
#define NTOK (NB * NT)

#define TOK_PER_BLK 64
#define NBLK (NTOK / TOK_PER_BLK)          // 512
#define CHUNKS_PER_B (NBLK / NB)           // 64

#define PHI_SCALE 0.17677669529663687f     // sqrt(2/64)

// Scratch (device globals — no allocation in kernel_launch)
__device__ float g_part[NBLK * NR];        // per-block partial phi_sum
__device__ float g_phisum[NB * NR];
__device__ float g_grav[NTOK];

// ---------------------------------------------------------------------------
// K1: per-block partial of phi_sum[b,r] = sum_t mass(t) * phi(t,r).
// 64 threads; thread tid owns feature r = tid. Weights staged in shared,
// w1 TRANSPOSED so the mainloop reads shared coalesced / broadcast only.
// phi is recomputed later — never stored.
// ---------------------------------------------------------------------------
__global__ void k_partial(const float* __restrict__ coords,
                          const float* __restrict__ w1,
                          const float* __restrict__ b1,
                          const float* __restrict__ w2,
                          const float* __restrict__ b2,
                          const float* __restrict__ W,
                          const float* __restrict__ bvec) {
    const int tid = threadIdx.x;           // 0..63
    const int bi  = blockIdx.x;            // 0..511
    const int tok0 = bi * TOK_PER_BLK;

    __shared__ float sw1t[ND * ND];        // sw1t[k*64+j] = w1[j*64+k]
    __shared__ float sW[ND * NR];          // W[k*64+r] (native layout)
    __shared__ float sb1[ND], sw2[ND], sbv[NR];
    __shared__ float sc[ND];
    __shared__ float red[ND];
    __shared__ float smass;

    for (int i = tid; i < ND * ND; i += 64) {
        const int k = i >> 6, j = i & 63;
        sw1t[i] = w1[j * ND + k];          // transpose on load
        sW[i]   = W[i];
    }
    sb1[tid] = b1[tid];
    sw2[tid] = w2[tid];
    sbv[tid] = bvec[tid];
    const float bias2 = b2[0];
    __syncthreads();

    float acc = 0.0f;

    for (int t = 0; t < TOK_PER_BLK; t++) {
        const int tok = tok0 + t;
        sc[tid] = coords[tok * ND + tid];
        __syncthreads();

        // h_tid = relu(b1 + coords . w1_row_tid); partial mass product
        float a = sb1[tid];
#pragma unroll
        for (int k = 0; k < ND; k++)
            a = fmaf(sc[k], sw1t[k * ND + tid], a);
        red[tid] = fmaxf(a, 0.0f) * sw2[tid];
        __syncthreads();

        if (tid < 32) {
            float s = red[tid] + red[tid + 32];
#pragma unroll
            for (int o = 16; o > 0; o >>= 1)
                s += __shfl_down_sync(0xffffffffu, s, o);
            if (tid == 0) {
                s += bias2;
                smass = (s > 20.0f) ? s : log1pf(expf(s));
            }
        }
        __syncthreads();

        // phi_tid, accumulate mass * phi
        float ang = sbv[tid];
#pragma unroll
        for (int k = 0; k < ND; k++)
            ang = fmaf(sc[k], sW[k * NR + tid], ang);
        acc = fmaf(smass, PHI_SCALE * cosf(ang), acc);
        __syncthreads();                   // protect sc before next token
    }

    g_part[bi * NR + tid] = acc;
}

// ---------------------------------------------------------------------------
// K2: phi_sum[b,r] = sum over 64 chunks of partials. 8 blocks x 64 threads.
// ---------------------------------------------------------------------------
__global__ void k_reduce() {
    const int b = blockIdx.x;
    const int r = threadIdx.x;
    float s = 0.0f;
#pragma unroll
    for (int c = 0; c < CHUNKS_PER_B; c++)
        s += g_part[(b * CHUNKS_PER_B + c) * NR + r];
    g_phisum[b * NR + r] = s;
}

// ---------------------------------------------------------------------------
// K3: grav[tok] = dot(phi(tok), phi_sum[b]). phi recomputed from coords.
// Same layout as K1: 512 blocks x 64 threads x 64 tokens.
// ---------------------------------------------------------------------------
__global__ void k_grav(const float* __restrict__ coords,
                       const float* __restrict__ W,
                       const float* __restrict__ bvec) {
    const int tid = threadIdx.x;
    const int bi  = blockIdx.x;
    const int tok0 = bi * TOK_PER_BLK;
    const int b    = bi / CHUNKS_PER_B;

    __shared__ float sW[ND * NR];
    __shared__ float sbv[NR], sps[NR];
    __shared__ float sc[ND];
    __shared__ float red[ND];

    for (int i = tid; i < ND * NR; i += 64)
        sW[i] = W[i];
    sbv[tid] = bvec[tid];
    sps[tid] = g_phisum[b * NR + tid];
    __syncthreads();

    for (int t = 0; t < TOK_PER_BLK; t++) {
        const int tok = tok0 + t;
        sc[tid] = coords[tok * ND + tid];
        __syncthreads();

        float ang = sbv[tid];
#pragma unroll
        for (int k = 0; k < ND; k++)
            ang = fmaf(sc[k], sW[k * NR + tid], ang);
        red[tid] = PHI_SCALE * cosf(ang) * sps[tid];
        __syncthreads();

        if (tid < 32) {
            float s = red[tid] + red[tid + 32];
#pragma unroll
            for (int o = 16; o > 0; o >>= 1)
                s += __shfl_down_sync(0xffffffffu, s, o);
            if (tid == 0) g_grav[tok] = s;
        }
        __syncthreads();
    }
}

// ---------------------------------------------------------------------------
// K4: out = G + 0.1 * grav * I  (unchanged — 85% DRAM, near roofline)
// ---------------------------------------------------------------------------
__global__ void k_out(const float4* __restrict__ G4, float4* __restrict__ O4) {
    const int token = blockIdx.x;
    const int tid   = threadIdx.x;

    const float add = 0.1f * g_grav[token];

    const float4* src = G4 + (size_t)token * 1024;
    float4*       dst = O4 + (size_t)token * 1024;

#pragma unroll
    for (int k = 0; k < 4; k++) {
        const int i4 = tid + k * 256;
        float4 v = src[i4];
        const int base = i4 * 4;
        if ((base    ) % 65 == 0) v.x += add;
        if ((base + 1) % 65 == 0) v.y += add;
        if ((base + 2) % 65 == 0) v.z += add;
        if ((base + 3) % 65 == 0) v.w += add;
        dst[i4] = v;
    }
}

// ---------------------------------------------------------------------------
extern "C" void kernel_launch(void* const* d_in, const int* in_sizes, int n_in,
                              void* d_out, int out_size) {
    const float* G      = (const float*)d_in[0];
    const float* coords = (const float*)d_in[1];
    const float* w1     = (const float*)d_in[2];
    const float* b1     = (const float*)d_in[3];
    const float* w2     = (const float*)d_in[4];
    const float* b2     = (const float*)d_in[5];
    const float* W      = (const float*)d_in[6];
    const float* bvec   = (const float*)d_in[7];

    k_partial<<<NBLK, 64>>>(coords, w1, b1, w2, b2, W, bvec);
    k_reduce<<<NB, NR>>>();
    k_grav<<<NBLK, 64>>>(coords, W, bvec);
    k_out<<<NTOK, 256>>>((const float4*)G, (float4*)d_out);
}